// round 9
// baseline (speedup 1.0000x reference)
#include <cuda_runtime.h>
#include <cstdint>

// CTC greedy decode:  probs [B, T=512, C=128] f32  ->  out [B, T] (float32 values)
// best[t] = argmax_c probs[b,t,c] (first-max tie-break, like jnp.argmax)
// valid[t] = best[t] != best[t-1] (prev=-1 at t=0)  &&  best[t] != C-1 (blank)
// out row  = table[best] for valid t (left-packed), tail = default_char.
//
// R7: output compared as float32 -> write float values.
// R8: REDUX argmax + 256-thr CTAs -> 45.6us, DRAM 76%.
// R9: manual 4x front-batched LDG.128 per warp (MLP_p1=4) + __ldcs streaming.

#define CTC_T 512
#define CTC_C 128
#define CTC_BLANK (CTC_C - 1)
#define CTC_THREADS 256
#define CTC_WARPS (CTC_THREADS / 32)
#define CTC_TPW (CTC_T / CTC_WARPS)   // timesteps per warp = 64
#define BATCH 4

// Order-preserving float->uint map (monotone for all finite floats).
__device__ __forceinline__ unsigned f2ord(float f) {
    unsigned u = __float_as_uint(f);
    return (u & 0x80000000u) ? ~u : (u | 0x80000000u);
}

template<bool VEC4>
__global__ __launch_bounds__(CTC_THREADS)
void ctc_decode_kernel(const float* __restrict__ probs,
                       const int* __restrict__ table,
                       const int* __restrict__ defc_ptr,
                       float* __restrict__ out,
                       long long n_probs_elems)
{
    __shared__ int   s_best[CTC_T];
    __shared__ int   s_wsum[CTC_WARPS];
    __shared__ float s_table[CTC_C];

    const int b    = blockIdx.x;
    const int tid  = threadIdx.x;
    const int lane = tid & 31;
    const int wid  = tid >> 5;

    // Bounds guard: never read past the probs buffer.
    if ((long long)(b + 1) * CTC_T * CTC_C > n_probs_elems) return;

    if (tid < CTC_C) s_table[tid] = (float)table[tid];

    const float* __restrict__ base = probs + (size_t)b * CTC_T * CTC_C;

    // ---- Phase 1: per-timestep argmax, one warp per timestep ----
    // Warp `wid` owns timesteps {wid + 8k}. Process BATCH=4 timesteps per
    // outer iteration: all 4 LDG.128s issue back-to-back (independent, so
    // they stay in flight together -> MLP_p1=4/warp), then the reductions run.
    if (VEC4) {
        #pragma unroll 2
        for (int k = 0; k < CTC_TPW; k += BATCH) {
            float4 v[BATCH];
            #pragma unroll
            for (int j = 0; j < BATCH; ++j) {
                const int t = wid + (k + j) * CTC_WARPS;
                v[j] = __ldcs(reinterpret_cast<const float4*>(base + t * CTC_C) + lane);
            }
            #pragma unroll
            for (int j = 0; j < BATCH; ++j) {
                const int t = wid + (k + j) * CTC_WARPS;
                float m  = v[j].x;  int mi = lane * 4;
                if (v[j].y > m) { m = v[j].y; mi = lane * 4 + 1; }
                if (v[j].z > m) { m = v[j].z; mi = lane * 4 + 2; }
                if (v[j].w > m) { m = v[j].w; mi = lane * 4 + 3; }
                // Warp argmax via REDUX: max of order-mapped value, then min
                // index among max-holding lanes (lowest-index tie-break).
                const unsigned mo   = f2ord(m);
                const unsigned vmax = __reduce_max_sync(0xffffffffu, mo);
                const unsigned cand = (mo == vmax) ? (unsigned)mi : 0xffffffffu;
                const unsigned imin = __reduce_min_sync(0xffffffffu, cand);
                if (lane == 0) s_best[t] = (int)imin;
            }
        }
    } else {
        // Coalesced scalar fallback (unaligned probs pointer).
        for (int t = wid; t < CTC_T; t += CTC_WARPS) {
            const float* row = base + t * CTC_C;
            float m  = __ldg(row + lane);  int mi = lane;
            #pragma unroll
            for (int kk = 1; kk < 4; ++kk) {
                int   c = lane + kk * 32;
                float vv = __ldg(row + c);
                if (vv > m) { m = vv; mi = c; }
            }
            const unsigned mo   = f2ord(m);
            const unsigned vmax = __reduce_max_sync(0xffffffffu, mo);
            const unsigned cand = (mo == vmax) ? (unsigned)mi : 0xffffffffu;
            const unsigned imin = __reduce_min_sync(0xffffffffu, cand);
            if (lane == 0) s_best[t] = (int)imin;
        }
    }
    __syncthreads();

    // ---- Phase 2: valid flags + block scan; thread owns timesteps 2t, 2t+1 ----
    const int t0 = 2 * tid, t1 = 2 * tid + 1;
    const int b0 = s_best[t0];
    const int b1 = s_best[t1];
    const int p0 = (t0 == 0) ? -1 : s_best[t0 - 1];
    const int v0 = (b0 != p0 && b0 != CTC_BLANK) ? 1 : 0;
    const int v1 = (b1 != b0 && b1 != CTC_BLANK) ? 1 : 0;
    const int pair = v0 + v1;

    int x = pair;
    #pragma unroll
    for (int off = 1; off < 32; off <<= 1) {
        int y = __shfl_up_sync(0xffffffffu, x, off);
        if (lane >= off) x += y;
    }
    if (lane == 31) s_wsum[wid] = x;
    __syncthreads();

    if (wid == 0) {
        int ws = (lane < CTC_WARPS) ? s_wsum[lane] : 0;
        #pragma unroll
        for (int off = 1; off < CTC_WARPS; off <<= 1) {
            int y = __shfl_up_sync(0xffffffffu, ws, off);
            if (lane >= off) ws += y;
        }
        if (lane < CTC_WARPS) s_wsum[lane] = ws;
    }
    __syncthreads();

    const int incl_pair = x + (wid > 0 ? s_wsum[wid - 1] : 0); // inclusive over pairs
    const int excl      = incl_pair - pair;                     // exclusive before t0
    const int count     = s_wsum[CTC_WARPS - 1];                // total valid in row
    const float defc    = defc_ptr ? (float)__ldg(defc_ptr) : 32.0f;

    float* __restrict__ orow = out + (size_t)b * CTC_T;
    if (v0) orow[excl]        = s_table[b0];   // packed positions
    if (v1) orow[excl + v0]   = s_table[b1];
    if (t0 >= count) orow[t0] = defc;          // tail padding (disjoint)
    if (t1 >= count) orow[t1] = defc;
}

extern "C" void kernel_launch(void* const* d_in, const int* in_sizes, int n_in,
                              void* d_out, int out_size)
{
    // --- bind inputs by size (elements-vs-bytes auto-detected) ---
    int probs_i = 0;
    long long max_sz = -1;
    for (int i = 0; i < n_in; ++i)
        if ((long long)in_sizes[i] > max_sz) { max_sz = in_sizes[i]; probs_i = i; }

    int table_i = -1, defc_i = -1;
    int scale = 1;
    for (int i = 0; i < n_in; ++i) {
        if (i == probs_i) continue;
        const int s = in_sizes[i];
        if (s == CTC_C)                          { table_i = i; scale = 1; }
        else if (s == CTC_C * 4 && table_i < 0)  { table_i = i; scale = 4; }
        else if (s == 1 || s == 4)               { if (defc_i < 0) defc_i = i; }
    }
    if (table_i < 0) { table_i = (probs_i == 0 && n_in > 1) ? 1 : 0; scale = 1; }

    const float* probs = (const float*)d_in[probs_i];
    const int*   table = (const int*)d_in[table_i];
    const int*   defc  = (defc_i >= 0) ? (const int*)d_in[defc_i] : nullptr;
    float*       out   = (float*)d_out;

    const long long probs_elems = max_sz / scale;
    int B = (int)(probs_elems / ((long long)CTC_T * CTC_C));
    if (B <= 0) return;

    const bool aligned16 = ((uintptr_t)probs & 15u) == 0;
    if (aligned16)
        ctc_decode_kernel<true ><<<B, CTC_THREADS>>>(probs, table, defc, out, probs_elems);
    else
        ctc_decode_kernel<false><<<B, CTC_THREADS>>>(probs, table, defc, out, probs_elems);
}

// round 10
// speedup vs baseline: 1.3546x; 1.3546x over previous
#include <cuda_runtime.h>
#include <cstdint>

// CTC greedy decode:  probs [B, T=512, C=128] f32  ->  out [B, T] (float32 values)
// best[t] = argmax_c probs[b,t,c] (first-max tie-break, like jnp.argmax)
// valid[t] = best[t] != best[t-1] (prev=-1 at t=0)  &&  best[t] != C-1 (blank)
// out row  = table[best] for valid t (left-packed), tail = default_char.
//
// R7: output compared as float32 -> write float values.
// R8: REDUX argmax + 256-thr CTAs -> 45.6us, DRAM 76%, occ 80%.
// R9: FAILED (batch4 + __ldcs): regs 39, occ 61%, DRAM 53% -> 66us. Reverted.
// R10: R8 + BATCH=2 front-batched __ldg LDG.128, launch_bounds(256,8) to pin
//      regs <= 32 so occupancy stays at R8 levels.

#define CTC_T 512
#define CTC_C 128
#define CTC_BLANK (CTC_C - 1)
#define CTC_THREADS 256
#define CTC_WARPS (CTC_THREADS / 32)
#define CTC_TPW (CTC_T / CTC_WARPS)   // timesteps per warp = 64
#define BATCH 2

// Order-preserving float->uint map (monotone for all finite floats).
__device__ __forceinline__ unsigned f2ord(float f) {
    unsigned u = __float_as_uint(f);
    return (u & 0x80000000u) ? ~u : (u | 0x80000000u);
}

template<bool VEC4>
__global__ __launch_bounds__(CTC_THREADS, 8)
void ctc_decode_kernel(const float* __restrict__ probs,
                       const int* __restrict__ table,
                       const int* __restrict__ defc_ptr,
                       float* __restrict__ out,
                       long long n_probs_elems)
{
    __shared__ int   s_best[CTC_T];
    __shared__ int   s_wsum[CTC_WARPS];
    __shared__ float s_table[CTC_C];

    const int b    = blockIdx.x;
    const int tid  = threadIdx.x;
    const int lane = tid & 31;
    const int wid  = tid >> 5;

    // Bounds guard: never read past the probs buffer.
    if ((long long)(b + 1) * CTC_T * CTC_C > n_probs_elems) return;

    if (tid < CTC_C) s_table[tid] = (float)table[tid];

    const float* __restrict__ base = probs + (size_t)b * CTC_T * CTC_C;

    // ---- Phase 1: per-timestep argmax, one warp per timestep ----
    // Warp `wid` owns timesteps {wid + 8k}. BATCH=2: issue 2 independent
    // LDG.128s back-to-back, then reduce both (keeps regs low, doubles
    // per-warp loads in flight vs R8).
    if (VEC4) {
        #pragma unroll 4
        for (int k = 0; k < CTC_TPW; k += BATCH) {
            float4 v0 = __ldg(reinterpret_cast<const float4*>(
                                  base + (wid + (k + 0) * CTC_WARPS) * CTC_C) + lane);
            float4 v1 = __ldg(reinterpret_cast<const float4*>(
                                  base + (wid + (k + 1) * CTC_WARPS) * CTC_C) + lane);
            #pragma unroll
            for (int j = 0; j < BATCH; ++j) {
                const float4 v = (j == 0) ? v0 : v1;
                const int t = wid + (k + j) * CTC_WARPS;
                float m  = v.x;  int mi = lane * 4;
                if (v.y > m) { m = v.y; mi = lane * 4 + 1; }
                if (v.z > m) { m = v.z; mi = lane * 4 + 2; }
                if (v.w > m) { m = v.w; mi = lane * 4 + 3; }
                // Warp argmax via REDUX: max of order-mapped value, then min
                // index among max-holding lanes (lowest-index tie-break).
                const unsigned mo   = f2ord(m);
                const unsigned vmax = __reduce_max_sync(0xffffffffu, mo);
                const unsigned cand = (mo == vmax) ? (unsigned)mi : 0xffffffffu;
                const unsigned imin = __reduce_min_sync(0xffffffffu, cand);
                if (lane == 0) s_best[t] = (int)imin;
            }
        }
    } else {
        // Coalesced scalar fallback (unaligned probs pointer).
        for (int t = wid; t < CTC_T; t += CTC_WARPS) {
            const float* row = base + t * CTC_C;
            float m  = __ldg(row + lane);  int mi = lane;
            #pragma unroll
            for (int kk = 1; kk < 4; ++kk) {
                int   c = lane + kk * 32;
                float vv = __ldg(row + c);
                if (vv > m) { m = vv; mi = c; }
            }
            const unsigned mo   = f2ord(m);
            const unsigned vmax = __reduce_max_sync(0xffffffffu, mo);
            const unsigned cand = (mo == vmax) ? (unsigned)mi : 0xffffffffu;
            const unsigned imin = __reduce_min_sync(0xffffffffu, cand);
            if (lane == 0) s_best[t] = (int)imin;
        }
    }
    __syncthreads();

    // ---- Phase 2: valid flags + block scan; thread owns timesteps 2t, 2t+1 ----
    const int t0 = 2 * tid, t1 = 2 * tid + 1;
    const int b0 = s_best[t0];
    const int b1 = s_best[t1];
    const int p0 = (t0 == 0) ? -1 : s_best[t0 - 1];
    const int v0 = (b0 != p0 && b0 != CTC_BLANK) ? 1 : 0;
    const int v1 = (b1 != b0 && b1 != CTC_BLANK) ? 1 : 0;
    const int pair = v0 + v1;

    int x = pair;
    #pragma unroll
    for (int off = 1; off < 32; off <<= 1) {
        int y = __shfl_up_sync(0xffffffffu, x, off);
        if (lane >= off) x += y;
    }
    if (lane == 31) s_wsum[wid] = x;
    __syncthreads();

    if (wid == 0) {
        int ws = (lane < CTC_WARPS) ? s_wsum[lane] : 0;
        #pragma unroll
        for (int off = 1; off < CTC_WARPS; off <<= 1) {
            int y = __shfl_up_sync(0xffffffffu, ws, off);
            if (lane >= off) ws += y;
        }
        if (lane < CTC_WARPS) s_wsum[lane] = ws;
    }
    __syncthreads();

    const int incl_pair = x + (wid > 0 ? s_wsum[wid - 1] : 0); // inclusive over pairs
    const int excl      = incl_pair - pair;                     // exclusive before t0
    const int count     = s_wsum[CTC_WARPS - 1];                // total valid in row
    const float defc    = defc_ptr ? (float)__ldg(defc_ptr) : 32.0f;

    float* __restrict__ orow = out + (size_t)b * CTC_T;
    if (v0) orow[excl]        = s_table[b0];   // packed positions
    if (v1) orow[excl + v0]   = s_table[b1];
    if (t0 >= count) orow[t0] = defc;          // tail padding (disjoint)
    if (t1 >= count) orow[t1] = defc;
}

extern "C" void kernel_launch(void* const* d_in, const int* in_sizes, int n_in,
                              void* d_out, int out_size)
{
    // --- bind inputs by size (elements-vs-bytes auto-detected) ---
    int probs_i = 0;
    long long max_sz = -1;
    for (int i = 0; i < n_in; ++i)
        if ((long long)in_sizes[i] > max_sz) { max_sz = in_sizes[i]; probs_i = i; }

    int table_i = -1, defc_i = -1;
    int scale = 1;
    for (int i = 0; i < n_in; ++i) {
        if (i == probs_i) continue;
        const int s = in_sizes[i];
        if (s == CTC_C)                          { table_i = i; scale = 1; }
        else if (s == CTC_C * 4 && table_i < 0)  { table_i = i; scale = 4; }
        else if (s == 1 || s == 4)               { if (defc_i < 0) defc_i = i; }
    }
    if (table_i < 0) { table_i = (probs_i == 0 && n_in > 1) ? 1 : 0; scale = 1; }

    const float* probs = (const float*)d_in[probs_i];
    const int*   table = (const int*)d_in[table_i];
    const int*   defc  = (defc_i >= 0) ? (const int*)d_in[defc_i] : nullptr;
    float*       out   = (float*)d_out;

    const long long probs_elems = max_sz / scale;
    int B = (int)(probs_elems / ((long long)CTC_T * CTC_C));
    if (B <= 0) return;

    const bool aligned16 = ((uintptr_t)probs & 15u) == 0;
    if (aligned16)
        ctc_decode_kernel<true ><<<B, CTC_THREADS>>>(probs, table, defc, out, probs_elems);
    else
        ctc_decode_kernel<false><<<B, CTC_THREADS>>>(probs, table, defc, out, probs_elems);
}